// round 2
// baseline (speedup 1.0000x reference)
#include <cuda_runtime.h>
#include <math.h>

#define T_TOK 1024
#define HID   2048
#define NE    32
#define TOPK  6
#define NGRP  8
#define TGRP  3
#define IR    1408          // routed intermediate
#define IS    2816          // shared intermediate (I * NSH)
#define CAP   384
#define RSCALE 16.0f

#define BM 64
#define BN 64
#define BK 16

// ---------------- scratch (device globals: allocation-free) ----------------
__device__ int   g_topk_idx[T_TOK * TOPK];
__device__ float g_topk_w  [T_TOK * TOPK];
__device__ int   g_cnt     [NE];
__device__ int   g_rowtok  [NE * CAP];
__device__ int   g_slot    [T_TOK * TOPK];
__device__ float g_act     [NE * CAP * IR];    // 69 MB: routed silu(g)*u
__device__ float g_y       [NE * CAP * HID];   // 100 MB: routed expert outputs
__device__ float g_acts    [T_TOK * IS];       // 11.5 MB: shared silu(g)*u

// ---------------- gate + routing (one block per token) ----------------
__global__ void k_gate(const float* __restrict__ x, const float* __restrict__ gw) {
    int t = blockIdx.x;
    __shared__ float xs[HID];
    __shared__ float lg[NE];
    const float* xr = x + (size_t)t * HID;
    for (int i = threadIdx.x; i < HID; i += 256) xs[i] = xr[i];
    __syncthreads();

    // 8 threads per expert compute the dot product
    int e = threadIdx.x >> 3, j = threadIdx.x & 7;
    const float* w = gw + (size_t)e * HID;
    float s = 0.f;
    for (int i = j * 4; i < HID; i += 32) {
        float4 xv = *(const float4*)(xs + i);
        float4 wv = *(const float4*)(w + i);
        s += xv.x * wv.x + xv.y * wv.y + xv.z * wv.z + xv.w * wv.w;
    }
    #pragma unroll
    for (int off = 4; off; off >>= 1) s += __shfl_down_sync(0xffffffffu, s, off, 8);
    if (j == 0) lg[e] = s;
    __syncthreads();

    if (threadIdx.x == 0) {
        // group scores = max over each group of 4
        float gsc[NGRP]; int keep[NGRP];
        #pragma unroll
        for (int g2 = 0; g2 < NGRP; g2++) {
            float m4 = lg[g2 * 4];
            m4 = fmaxf(m4, lg[g2 * 4 + 1]);
            m4 = fmaxf(m4, lg[g2 * 4 + 2]);
            m4 = fmaxf(m4, lg[g2 * 4 + 3]);
            gsc[g2] = m4; keep[g2] = 0;
        }
        // top-3 groups (strict >, ascending scan == lax.top_k tie rule)
        for (int it = 0; it < TGRP; it++) {
            float best = -INFINITY; int bi = 0;
            for (int g2 = 0; g2 < NGRP; g2++)
                if (!keep[g2] && gsc[g2] > best) { best = gsc[g2]; bi = g2; }
            keep[bi] = 1;
        }
        // masked scores (non-kept -> 0.0 !) then softmax over all 32
        float sc[NE]; float mx = -INFINITY;
        for (int e2 = 0; e2 < NE; e2++) {
            float v = keep[e2 >> 2] ? lg[e2] : 0.0f;
            sc[e2] = v; mx = fmaxf(mx, v);
        }
        float sum = 0.f;
        for (int e2 = 0; e2 < NE; e2++) { float p = expf(sc[e2] - mx); sc[e2] = p; sum += p; }
        // top-6 of probs (unnormalized exp has identical ordering & ties)
        unsigned taken = 0u;
        for (int it = 0; it < TOPK; it++) {
            float best = -1.f; int bi = 0;
            for (int e2 = 0; e2 < NE; e2++)
                if (!((taken >> e2) & 1u) && sc[e2] > best) { best = sc[e2]; bi = e2; }
            taken |= 1u << bi;
            g_topk_idx[t * TOPK + it] = bi;
            g_topk_w  [t * TOPK + it] = (best / sum) * RSCALE;
        }
    }
}

// ---------------- dispatch: flat-order capacity positions (warp e scans all) ----------------
__global__ void k_dispatch() {
    int w = threadIdx.x >> 5, lane = threadIdx.x & 31;
    int count = 0;
    for (int base = 0; base < T_TOK * TOPK; base += 32) {
        int idx = g_topk_idx[base + lane];
        unsigned m = __ballot_sync(0xffffffffu, idx == w);
        if (idx == w) {
            int pos = count + __popc(m & ((1u << lane) - 1u));
            int s = -1;
            if (pos < CAP) { s = w * CAP + pos; g_rowtok[s] = (base + lane) / TOPK; }
            g_slot[base + lane] = s;
        }
        count += __popc(m);
    }
    if (lane == 0) g_cnt[w] = count;
}

// ---------------- GEMM: A[rows,K] @ B[K,2*Nhalf] with fused silu(g)*u ----------------
__device__ __forceinline__ void gemm_gateup(
    const float* __restrict__ A, const int* __restrict__ rowtok,
    const int* __restrict__ cnt, const float* __restrict__ B,
    float* __restrict__ Cout, int lda, int Kdim, int Nhalf, int ldb,
    int tilesM, int cap)
{
    int e  = blockIdx.y / tilesM;
    int mt = blockIdx.y - e * tilesM;
    int rows = cnt ? min(cnt[e], cap) : cap;
    int m0 = mt * BM;
    if (m0 >= rows) return;

    __shared__ float As[BK][BM + 4];
    __shared__ float Bg[BK][BN];
    __shared__ float Bu[BK][BN];
    __shared__ int   rix[BM];

    int tid = threadIdx.x;
    if (tid < BM) {
        int gm = m0 + tid;
        rix[tid] = (gm < rows) ? (rowtok ? rowtok[e * cap + gm] : gm) : -1;
    }
    __syncthreads();

    int ar = tid >> 2, ak = (tid & 3) << 2;    // A loader: row, k-offset
    int br = tid >> 4, bn = (tid & 15) << 2;   // B loader: k-row, n-offset
    int tx = tid & 15, ty = tid >> 4;          // compute microtile coords

    int rt = rix[ar];
    const float* Ap = (rt >= 0) ? (A + (size_t)rt * lda + ak) : A;
    bool aval = (rt >= 0);
    const float* Bp = B + (size_t)e * Kdim * ldb + (size_t)br * ldb
                        + (size_t)blockIdx.x * BN + bn;

    float accg[16], accu[16];
    #pragma unroll
    for (int i = 0; i < 16; i++) { accg[i] = 0.f; accu[i] = 0.f; }

    for (int k0 = 0; k0 < Kdim; k0 += BK) {
        float4 av = make_float4(0.f, 0.f, 0.f, 0.f);
        if (aval) av = *(const float4*)(Ap + k0);
        const float* bp = Bp + (size_t)k0 * ldb;
        float4 bgv = *(const float4*)bp;
        float4 buv = *(const float4*)(bp + Nhalf);
        __syncthreads();
        As[ak][ar] = av.x; As[ak + 1][ar] = av.y; As[ak + 2][ar] = av.z; As[ak + 3][ar] = av.w;
        *(float4*)&Bg[br][bn] = bgv;
        *(float4*)&Bu[br][bn] = buv;
        __syncthreads();
        #pragma unroll
        for (int kk = 0; kk < BK; kk++) {
            float4 a  = *(const float4*)&As[kk][ty << 2];
            float4 bg = *(const float4*)&Bg[kk][tx << 2];
            float4 bu = *(const float4*)&Bu[kk][tx << 2];
            float aa[4] = {a.x, a.y, a.z, a.w};
            float gg[4] = {bg.x, bg.y, bg.z, bg.w};
            float uu[4] = {bu.x, bu.y, bu.z, bu.w};
            #pragma unroll
            for (int i = 0; i < 4; i++)
                #pragma unroll
                for (int jj = 0; jj < 4; jj++) {
                    accg[i * 4 + jj] += aa[i] * gg[jj];
                    accu[i * 4 + jj] += aa[i] * uu[jj];
                }
        }
    }

    float* Ce = Cout + (size_t)e * cap * Nhalf + (size_t)blockIdx.x * BN + (tx << 2);
    #pragma unroll
    for (int i = 0; i < 4; i++) {
        int gm = m0 + (ty << 2) + i;
        if (gm >= rows) break;
        float4 o; float g, u;
        g = accg[i * 4 + 0]; u = accu[i * 4 + 0]; o.x = u * g / (1.f + expf(-g));
        g = accg[i * 4 + 1]; u = accu[i * 4 + 1]; o.y = u * g / (1.f + expf(-g));
        g = accg[i * 4 + 2]; u = accu[i * 4 + 2]; o.z = u * g / (1.f + expf(-g));
        g = accg[i * 4 + 3]; u = accu[i * 4 + 3]; o.w = u * g / (1.f + expf(-g));
        *(float4*)(Ce + (size_t)gm * Nhalf) = o;
    }
}

// ---------------- plain GEMM: A[rows,K] @ B[K,N] ----------------
__device__ __forceinline__ void gemm_plain(
    const float* __restrict__ A, const int* __restrict__ cnt,
    const float* __restrict__ B, float* __restrict__ Cout,
    int lda, int Kdim, int N, int ldb, int tilesM, int cap)
{
    int e  = blockIdx.y / tilesM;
    int mt = blockIdx.y - e * tilesM;
    int rows = cnt ? min(cnt[e], cap) : cap;
    int m0 = mt * BM;
    if (m0 >= rows) return;

    __shared__ float As[BK][BM + 4];
    __shared__ float Bs[BK][BN];

    int tid = threadIdx.x;
    int ar = tid >> 2, ak = (tid & 3) << 2;
    int br = tid >> 4, bn = (tid & 15) << 2;
    int tx = tid & 15, ty = tid >> 4;

    const float* Ap = A + (size_t)e * cap * lda + (size_t)(m0 + ar) * lda + ak;
    const float* Bp = B + (size_t)e * Kdim * ldb + (size_t)br * ldb
                        + (size_t)blockIdx.x * BN + bn;

    float acc[16];
    #pragma unroll
    for (int i = 0; i < 16; i++) acc[i] = 0.f;

    for (int k0 = 0; k0 < Kdim; k0 += BK) {
        float4 av = *(const float4*)(Ap + k0);
        float4 bv = *(const float4*)(Bp + (size_t)k0 * ldb);
        __syncthreads();
        As[ak][ar] = av.x; As[ak + 1][ar] = av.y; As[ak + 2][ar] = av.z; As[ak + 3][ar] = av.w;
        *(float4*)&Bs[br][bn] = bv;
        __syncthreads();
        #pragma unroll
        for (int kk = 0; kk < BK; kk++) {
            float4 a = *(const float4*)&As[kk][ty << 2];
            float4 b = *(const float4*)&Bs[kk][tx << 2];
            float aa[4] = {a.x, a.y, a.z, a.w};
            float bb[4] = {b.x, b.y, b.z, b.w};
            #pragma unroll
            for (int i = 0; i < 4; i++)
                #pragma unroll
                for (int jj = 0; jj < 4; jj++)
                    acc[i * 4 + jj] += aa[i] * bb[jj];
        }
    }

    float* Ce = Cout + (size_t)e * cap * N + (size_t)blockIdx.x * BN + (tx << 2);
    #pragma unroll
    for (int i = 0; i < 4; i++) {
        int gm = m0 + (ty << 2) + i;
        if (gm >= rows) break;
        float4 o = make_float4(acc[i * 4], acc[i * 4 + 1], acc[i * 4 + 2], acc[i * 4 + 3]);
        *(float4*)(Ce + (size_t)gm * N) = o;
    }
}

// ---------------- wrappers binding device-global scratch ----------------
__global__ void k_gemm1_routed(const float* __restrict__ x, const float* __restrict__ wgu) {
    gemm_gateup(x, g_rowtok, g_cnt, wgu, g_act, HID, HID, IR, 2 * IR, CAP / BM, CAP);
}
__global__ void k_gemm1_shared(const float* __restrict__ x, const float* __restrict__ wsgu) {
    gemm_gateup(x, nullptr, nullptr, wsgu, g_acts, HID, HID, IS, 2 * IS, T_TOK / BM, T_TOK);
}
__global__ void k_gemm2_routed(const float* __restrict__ wd) {
    gemm_plain(g_act, g_cnt, wd, g_y, IR, IR, HID, HID, CAP / BM, CAP);
}
__global__ void k_gemm2_shared(float* __restrict__ out, const float* __restrict__ wsd) {
    gemm_plain(g_acts, nullptr, wsd, out, IS, IS, HID, HID, T_TOK / BM, T_TOK);
}

// ---------------- combine: out[t] = shared[t] + sum_k w_k * y[slot_k] ----------------
__global__ void k_combine(float* __restrict__ out) {
    int idx = blockIdx.x * 256 + threadIdx.x;      // one float4 per thread
    int t = idx >> 9;                              // 512 float4 per token
    int h = (idx & 511) << 2;
    float* op = out + (size_t)t * HID + h;
    float4 acc = *(float4*)op;                     // shared-expert value already written
    #pragma unroll
    for (int k = 0; k < TOPK; k++) {
        int s = g_slot[t * TOPK + k];
        if (s >= 0) {
            float wv = g_topk_w[t * TOPK + k];
            float4 y = *(const float4*)(g_y + (size_t)s * HID + h);
            acc.x += wv * y.x; acc.y += wv * y.y; acc.z += wv * y.z; acc.w += wv * y.w;
        }
    }
    *(float4*)op = acc;
}

// ---------------- entry ----------------
extern "C" void kernel_launch(void* const* d_in, const int* in_sizes, int n_in,
                              void* d_out, int out_size) {
    const float* x    = (const float*)d_in[0];   // [1,1024,2048]
    const float* gw   = (const float*)d_in[1];   // [32,2048]
    const float* wgu  = (const float*)d_in[2];   // [32,2048,2816]
    const float* wd   = (const float*)d_in[3];   // [32,1408,2048]
    const float* wsgu = (const float*)d_in[4];   // [2048,5632]
    const float* wsd  = (const float*)d_in[5];   // [2816,2048]
    float* out = (float*)d_out;                  // [1024,2048] fp32

    k_gate    <<<T_TOK, 256>>>(x, gw);
    k_dispatch<<<1, 1024>>>();
    k_gemm1_routed<<<dim3(IR  / BN, NE * (CAP / BM)), 256>>>(x, wgu);
    k_gemm2_routed<<<dim3(HID / BN, NE * (CAP / BM)), 256>>>(wd);
    k_gemm1_shared<<<dim3(IS  / BN, T_TOK / BM), 256>>>(x, wsgu);
    k_gemm2_shared<<<dim3(HID / BN, T_TOK / BM), 256>>>(out, wsd);
    k_combine <<<(T_TOK * HID / 4) / 256, 256>>>(out);
}

// round 4
// speedup vs baseline: 1.8768x; 1.8768x over previous
#include <cuda_runtime.h>
#include <cuda_bf16.h>
#include <math.h>
#include <stdint.h>

#define T_TOK 1024
#define HID   2048
#define NE    32
#define TOPK  6
#define NGRP  8
#define TGRP  3
#define IR    1408
#define IS    2816
#define CAP   384
#define RSCALE 16.0f

#define STAGE_BYTES 32768          // A 16KB + B 16KB
#define SMEM_DYN    65536          // 2 stages; reused as 128x128 fp32 epilogue

// ---------------- scratch (device globals: allocation-free) ----------------
__device__ int   g_topk_idx[T_TOK * TOPK];
__device__ float g_topk_w  [T_TOK * TOPK];
__device__ int   g_cnt     [NE];
__device__ int   g_rowtok  [NE * CAP];
__device__ int   g_slot    [T_TOK * TOPK];
__device__ float g_y       [(size_t)NE * CAP * HID];
__device__ unsigned short g_act_hi [(size_t)NE * CAP * IR];
__device__ unsigned short g_act_lo [(size_t)NE * CAP * IR];
__device__ unsigned short g_sact_hi[(size_t)T_TOK * IS];
__device__ unsigned short g_sact_lo[(size_t)T_TOK * IS];

// ---------------- helpers ----------------
__device__ __forceinline__ uint32_t smem_u32(const void* p) {
    uint32_t a;
    asm("{ .reg .u64 t; cvta.to.shared.u64 t, %1; cvt.u32.u64 %0, t; }" : "=r"(a) : "l"(p));
    return a;
}
#define SWZ(o) ((uint32_t)(o) ^ ((((uint32_t)(o)) >> 3) & 0x70u))

__device__ __forceinline__ void ldsm4(uint32_t* r, uint32_t a) {
    asm volatile("ldmatrix.sync.aligned.m8n8.x4.shared.b16 {%0,%1,%2,%3}, [%4];"
        : "=r"(r[0]), "=r"(r[1]), "=r"(r[2]), "=r"(r[3]) : "r"(a));
}
__device__ __forceinline__ void ldsm4t(uint32_t* r, uint32_t a) {
    asm volatile("ldmatrix.sync.aligned.m8n8.x4.trans.shared.b16 {%0,%1,%2,%3}, [%4];"
        : "=r"(r[0]), "=r"(r[1]), "=r"(r[2]), "=r"(r[3]) : "r"(a));
}
__device__ __forceinline__ void mma16816(float* c, const uint32_t* a, const uint32_t* b) {
    asm volatile("mma.sync.aligned.m16n8k16.row.col.f32.bf16.bf16.f32 "
        "{%0,%1,%2,%3}, {%4,%5,%6,%7}, {%8,%9}, {%0,%1,%2,%3};"
        : "+f"(c[0]), "+f"(c[1]), "+f"(c[2]), "+f"(c[3])
        : "r"(a[0]), "r"(a[1]), "r"(a[2]), "r"(a[3]), "r"(b[0]), "r"(b[1]));
}

__device__ __forceinline__ void bsplit(float f, unsigned short& h, unsigned short& l) {
    __nv_bfloat16 bh = __float2bfloat16_rn(f);
    float fh = __bfloat162float(bh);
    __nv_bfloat16 bl = __float2bfloat16_rn(f - fh);
    h = __bfloat16_as_ushort(bh);
    l = __bfloat16_as_ushort(bl);
}
__device__ __forceinline__ uint32_t pack2(unsigned short a, unsigned short b) {
    return (uint32_t)a | ((uint32_t)b << 16);
}
// split a float4 into 8B hi + 8B lo
__device__ __forceinline__ void split4(float4 v, uint2& h, uint2& l) {
    unsigned short h0,l0,h1,l1,h2,l2,h3,l3;
    bsplit(v.x,h0,l0); bsplit(v.y,h1,l1); bsplit(v.z,h2,l2); bsplit(v.w,h3,l3);
    h = make_uint2(pack2(h0,h1), pack2(h2,h3));
    l = make_uint2(pack2(l0,l1), pack2(l2,l3));
}

// ---------------- gate + routing (validated) ----------------
__global__ void k_gate(const float* __restrict__ x, const float* __restrict__ gw) {
    int t = blockIdx.x;
    __shared__ float xs[HID];
    __shared__ float lg[NE];
    const float* xr = x + (size_t)t * HID;
    for (int i = threadIdx.x; i < HID; i += 256) xs[i] = xr[i];
    __syncthreads();
    int e = threadIdx.x >> 3, j = threadIdx.x & 7;
    const float* w = gw + (size_t)e * HID;
    float s = 0.f;
    for (int i = j * 4; i < HID; i += 32) {
        float4 xv = *(const float4*)(xs + i);
        float4 wv = *(const float4*)(w + i);
        s += xv.x * wv.x + xv.y * wv.y + xv.z * wv.z + xv.w * wv.w;
    }
    #pragma unroll
    for (int off = 4; off; off >>= 1) s += __shfl_down_sync(0xffffffffu, s, off, 8);
    if (j == 0) lg[e] = s;
    __syncthreads();
    if (threadIdx.x == 0) {
        float gsc[NGRP]; int keep[NGRP];
        #pragma unroll
        for (int g2 = 0; g2 < NGRP; g2++) {
            float m4 = fmaxf(fmaxf(lg[g2*4], lg[g2*4+1]), fmaxf(lg[g2*4+2], lg[g2*4+3]));
            gsc[g2] = m4; keep[g2] = 0;
        }
        for (int it = 0; it < TGRP; it++) {
            float best = -INFINITY; int bi = 0;
            for (int g2 = 0; g2 < NGRP; g2++)
                if (!keep[g2] && gsc[g2] > best) { best = gsc[g2]; bi = g2; }
            keep[bi] = 1;
        }
        float sc[NE]; float mx = -INFINITY;
        for (int e2 = 0; e2 < NE; e2++) {
            float v = keep[e2 >> 2] ? lg[e2] : 0.0f;
            sc[e2] = v; mx = fmaxf(mx, v);
        }
        float sum = 0.f;
        for (int e2 = 0; e2 < NE; e2++) { float p = expf(sc[e2] - mx); sc[e2] = p; sum += p; }
        unsigned taken = 0u;
        for (int it = 0; it < TOPK; it++) {
            float best = -1.f; int bi = 0;
            for (int e2 = 0; e2 < NE; e2++)
                if (!((taken >> e2) & 1u) && sc[e2] > best) { best = sc[e2]; bi = e2; }
            taken |= 1u << bi;
            g_topk_idx[t * TOPK + it] = bi;
            g_topk_w  [t * TOPK + it] = (best / sum) * RSCALE;
        }
    }
}

__global__ void k_dispatch() {
    int w = threadIdx.x >> 5, lane = threadIdx.x & 31;
    int count = 0;
    for (int base = 0; base < T_TOK * TOPK; base += 32) {
        int idx = g_topk_idx[base + lane];
        unsigned m = __ballot_sync(0xffffffffu, idx == w);
        if (idx == w) {
            int pos = count + __popc(m & ((1u << lane) - 1u));
            int s = -1;
            if (pos < CAP) { s = w * CAP + pos; g_rowtok[s] = (base + lane) / TOPK; }
            g_slot[base + lane] = s;
        }
        count += __popc(m);
    }
    if (lane == 0) g_cnt[w] = count;
}

// =======================================================================
// Shared MMA mainloop (macro-ish via inline): CTA 128x128, 8 warps (2Mx4N),
// K-chunk 32, bf16 split 3-product, SW128 smem, 2-stage double buffer.
// SMEM stage layout: A: [128 rows][128B: hi(64B)|lo(64B)] = 16KB
//                    B: half h in {0,1}: hi 32x128B (4KB) @16384+h*8192, lo @+4096
// =======================================================================
struct Frag { float c[4][4][4]; };

__device__ __forceinline__ void mma_chunk(char* stg, uint32_t sbs, int wm, int wn, int lane,
                                          Frag& F) {
    uint32_t Bh = sbs + 16384u + (uint32_t)(wn >> 1) * 8192u;
    #pragma unroll
    for (int kk = 0; kk < 2; kk++) {
        uint32_t ah[4][4], al[4][4], bh[2][4], bl[2][4];
        #pragma unroll
        for (int mi = 0; mi < 4; mi++) {
            uint32_t ro = (uint32_t)((wm * 64 + mi * 16 + (lane & 15)) * 128
                                     + kk * 32 + ((lane >> 4) * 16));
            ldsm4(ah[mi], sbs + SWZ(ro));
            ldsm4(al[mi], sbs + SWZ(ro + 64));
        }
        #pragma unroll
        for (int ng = 0; ng < 2; ng++) {
            uint32_t ro = (uint32_t)((kk * 16 + (lane & 15)) * 128
                                     + (wn & 1) * 64 + ng * 32 + ((lane >> 4) * 16));
            ldsm4t(bh[ng], Bh + SWZ(ro));
            ldsm4t(bl[ng], Bh + 4096u + SWZ(ro));
        }
        #pragma unroll
        for (int mi = 0; mi < 4; mi++)
            #pragma unroll
            for (int ni = 0; ni < 4; ni++) {
                const uint32_t* bhp = &bh[ni >> 1][(ni & 1) * 2];
                const uint32_t* blp = &bl[ni >> 1][(ni & 1) * 2];
                mma16816(F.c[mi][ni], ah[mi], bhp);
                mma16816(F.c[mi][ni], ah[mi], blp);
                mma16816(F.c[mi][ni], al[mi], bhp);
            }
    }
}

__device__ __forceinline__ void stage_accum(float* ep, int wm, int wn, int lane, Frag& F) {
    #pragma unroll
    for (int mi = 0; mi < 4; mi++)
        #pragma unroll
        for (int ni = 0; ni < 4; ni++) {
            int row = wm * 64 + mi * 16 + (lane >> 2);
            int col = wn * 32 + ni * 8 + ((lane & 3) << 1);
            ep[row * 128 + col]       = F.c[mi][ni][0];
            ep[row * 128 + col + 1]   = F.c[mi][ni][1];
            ep[(row + 8) * 128 + col]     = F.c[mi][ni][2];
            ep[(row + 8) * 128 + col + 1] = F.c[mi][ni][3];
        }
}

// =======================================================================
// gate_up GEMM + fused SiLU -> bf16 hi/lo activations
// B gmem: [Kdim][2*Ihalf]; CTA covers gate cols [cb,cb+64) and up cols [Ihalf+cb,...)
// =======================================================================
__global__ void __launch_bounds__(256, 1)
k_mma_gateup(const float* __restrict__ X, const float* __restrict__ B,
             int routed, int cap, int tilesM, int Kdim, int Ihalf)
{
    extern __shared__ char dsm[];
    __shared__ int rix_s[128];
    const int ldb = 2 * Ihalf;
    int tid = threadIdx.x, wid = tid >> 5, lane = tid & 31;
    int wm = wid & 1, wn = wid >> 1;
    int e = blockIdx.y / tilesM, mt = blockIdx.y % tilesM;
    int cb = blockIdx.x * 64;
    int rows = routed ? min(g_cnt[e], cap) : cap;
    int m0 = mt * 128;
    if (m0 >= rows) return;

    if (tid < 128) {
        int gm = m0 + tid;
        rix_s[tid] = (gm < rows) ? (routed ? g_rowtok[e * CAP + gm] : gm) : -1;
    }
    __syncthreads();

    uint32_t sb = smem_u32(dsm);
    const float* Bb = B + (size_t)e * Kdim * ldb;
    const int NCH = Kdim >> 5;

    Frag F;
    #pragma unroll
    for (int mi = 0; mi < 4; mi++)
        #pragma unroll
        for (int ni = 0; ni < 4; ni++)
            #pragma unroll
            for (int q = 0; q < 4; q++) F.c[mi][ni][q] = 0.f;

    int arow = tid >> 3, ak4 = tid & 7;          // A loader coords
    int bkr = tid >> 4, bn4 = tid & 15;          // B loader coords
    float4 av[4], bv[4];

    // ---- prologue: load + stage chunk 0
    {
        #pragma unroll
        for (int i = 0; i < 4; i++) {
            int rt = rix_s[arow + i * 32];
            av[i] = (rt >= 0) ? *(const float4*)(X + (size_t)rt * Kdim + ak4 * 4)
                              : make_float4(0.f, 0.f, 0.f, 0.f);
        }
        #pragma unroll
        for (int h = 0; h < 2; h++)
            #pragma unroll
            for (int j = 0; j < 2; j++)
                bv[h * 2 + j] = *(const float4*)(Bb + (size_t)(bkr + j * 16) * ldb
                                                 + h * Ihalf + cb + bn4 * 4);
    }
    for (int c = 0; c < NCH; c++) {
        char* stg = dsm + (c & 1) * STAGE_BYTES;
        // STS current chunk from regs
        #pragma unroll
        for (int i = 0; i < 4; i++) {
            uint2 h2, l2; split4(av[i], h2, l2);
            int r = arow + i * 32;
            *(uint2*)(stg + SWZ(r * 128 + ak4 * 8)) = h2;
            *(uint2*)(stg + SWZ(r * 128 + 64 + ak4 * 8)) = l2;
        }
        #pragma unroll
        for (int h = 0; h < 2; h++)
            #pragma unroll
            for (int j = 0; j < 2; j++) {
                uint2 h2, l2; split4(bv[h * 2 + j], h2, l2);
                char* bb = stg + 16384 + h * 8192;
                uint32_t o = SWZ((bkr + j * 16) * 128 + bn4 * 8);
                *(uint2*)(bb + o) = h2;
                *(uint2*)(bb + 4096 + o) = l2;
            }
        __syncthreads();
        // LDG next chunk (latency hidden under MMA)
        if (c + 1 < NCH) {
            int k0 = (c + 1) << 5;
            #pragma unroll
            for (int i = 0; i < 4; i++) {
                int rt = rix_s[arow + i * 32];
                av[i] = (rt >= 0) ? *(const float4*)(X + (size_t)rt * Kdim + k0 + ak4 * 4)
                                  : make_float4(0.f, 0.f, 0.f, 0.f);
            }
            #pragma unroll
            for (int h = 0; h < 2; h++)
                #pragma unroll
                for (int j = 0; j < 2; j++)
                    bv[h * 2 + j] = *(const float4*)(Bb + (size_t)(k0 + bkr + j * 16) * ldb
                                                     + h * Ihalf + cb + bn4 * 4);
        }
        mma_chunk(stg, smem_u32(stg), wm, wn, lane, F);
        __syncthreads();
    }

    // ---- epilogue: accum -> smem fp32, silu(g)*u -> bf16 hi/lo -> gmem
    float* ep = (float*)dsm;
    stage_accum(ep, wm, wn, lane, F);
    __syncthreads();

    int m = tid >> 1, cs = (tid & 1) << 5;
    int rg = m0 + m;
    if (rg < rows) {
        unsigned short* Oh = routed ? g_act_hi : g_sact_hi;
        unsigned short* Ol = routed ? g_act_lo : g_sact_lo;
        size_t rowoff = ((size_t)(routed ? e * CAP : 0) + rg) * Ihalf + cb + cs;
        const float* gp = ep + m * 128 + cs;
        const float* up = gp + 64;
        uint32_t hi[16], lo[16];
        #pragma unroll
        for (int j = 0; j < 16; j++) {
            float g0 = gp[2*j],   u0 = up[2*j];
            float g1 = gp[2*j+1], u1 = up[2*j+1];
            float s0 = u0 * g0 / (1.f + expf(-g0));
            float s1 = u1 * g1 / (1.f + expf(-g1));
            unsigned short h0, l0, h1, l1;
            bsplit(s0, h0, l0); bsplit(s1, h1, l1);
            hi[j] = pack2(h0, h1); lo[j] = pack2(l0, l1);
        }
        #pragma unroll
        for (int j = 0; j < 4; j++) {
            *(uint4*)(Oh + rowoff + j * 8) = *(uint4*)(hi + j * 4);
            *(uint4*)(Ol + rowoff + j * 8) = *(uint4*)(lo + j * 4);
        }
    }
}

// =======================================================================
// down GEMM: act(bf16 hi/lo) @ Wd[K][HID] -> fp32
// =======================================================================
__global__ void __launch_bounds__(256, 1)
k_mma_down(const float* __restrict__ B, float* __restrict__ Oext,
           int routed, int cap, int tilesM, int Kdim)
{
    extern __shared__ char dsm[];
    int tid = threadIdx.x, wid = tid >> 5, lane = tid & 31;
    int wm = wid & 1, wn = wid >> 1;
    int e = blockIdx.y / tilesM, mt = blockIdx.y % tilesM;
    int n0 = blockIdx.x * 128;
    int rows = routed ? min(g_cnt[e], cap) : cap;
    int m0 = mt * 128;
    if (m0 >= rows) return;

    const unsigned short* Ah = routed ? g_act_hi : g_sact_hi;
    const unsigned short* Al = routed ? g_act_lo : g_sact_lo;
    size_t abase = ((size_t)(routed ? e * CAP : 0) + m0) * Kdim;
    const float* Bb = B + (size_t)e * Kdim * HID;
    const int NCH = Kdim >> 5;

    Frag F;
    #pragma unroll
    for (int mi = 0; mi < 4; mi++)
        #pragma unroll
        for (int ni = 0; ni < 4; ni++)
            #pragma unroll
            for (int q = 0; q < 4; q++) F.c[mi][ni][q] = 0.f;

    int arow = tid >> 2, aq = tid & 3;
    int bkr = tid >> 4, bn4 = tid & 15;
    uint4 ahv[2], alv[2];
    float4 bv[4];

    {
        #pragma unroll
        for (int i = 0; i < 2; i++) {
            size_t off = abase + (size_t)(arow + i * 64) * Kdim + aq * 8;
            ahv[i] = *(const uint4*)(Ah + off);
            alv[i] = *(const uint4*)(Al + off);
        }
        #pragma unroll
        for (int h = 0; h < 2; h++)
            #pragma unroll
            for (int j = 0; j < 2; j++)
                bv[h * 2 + j] = *(const float4*)(Bb + (size_t)(bkr + j * 16) * HID
                                                 + n0 + h * 64 + bn4 * 4);
    }
    for (int c = 0; c < NCH; c++) {
        char* stg = dsm + (c & 1) * STAGE_BYTES;
        #pragma unroll
        for (int i = 0; i < 2; i++) {
            int r = arow + i * 64;
            *(uint4*)(stg + SWZ(r * 128 + aq * 16)) = ahv[i];
            *(uint4*)(stg + SWZ(r * 128 + 64 + aq * 16)) = alv[i];
        }
        #pragma unroll
        for (int h = 0; h < 2; h++)
            #pragma unroll
            for (int j = 0; j < 2; j++) {
                uint2 h2, l2; split4(bv[h * 2 + j], h2, l2);
                char* bb = stg + 16384 + h * 8192;
                uint32_t o = SWZ((bkr + j * 16) * 128 + bn4 * 8);
                *(uint2*)(bb + o) = h2;
                *(uint2*)(bb + 4096 + o) = l2;
            }
        __syncthreads();
        if (c + 1 < NCH) {
            int k0 = (c + 1) << 5;
            #pragma unroll
            for (int i = 0; i < 2; i++) {
                size_t off = abase + (size_t)(arow + i * 64) * Kdim + k0 + aq * 8;
                ahv[i] = *(const uint4*)(Ah + off);
                alv[i] = *(const uint4*)(Al + off);
            }
            #pragma unroll
            for (int h = 0; h < 2; h++)
                #pragma unroll
                for (int j = 0; j < 2; j++)
                    bv[h * 2 + j] = *(const float4*)(Bb + (size_t)(k0 + bkr + j * 16) * HID
                                                     + n0 + h * 64 + bn4 * 4);
        }
        mma_chunk(stg, smem_u32(stg), wm, wn, lane, F);
        __syncthreads();
    }

    // ---- epilogue: accum -> smem -> coalesced fp32 stores
    float* ep = (float*)dsm;
    stage_accum(ep, wm, wn, lane, F);
    __syncthreads();

    int m = tid >> 1, cs = (tid & 1) << 6;
    int rg = m0 + m;
    if (rg < rows) {
        float* O = routed ? g_y : Oext;
        float* op = O + ((size_t)(routed ? e * CAP : 0) + rg) * HID + n0 + cs;
        const float* sp = ep + m * 128 + cs;
        #pragma unroll
        for (int j = 0; j < 16; j++)
            *(float4*)(op + j * 4) = *(const float4*)(sp + j * 4);
    }
}

// ---------------- combine ----------------
__global__ void k_combine(float* __restrict__ out) {
    int idx = blockIdx.x * 256 + threadIdx.x;
    int t = idx >> 9;
    int h = (idx & 511) << 2;
    float* op = out + (size_t)t * HID + h;
    float4 acc = *(float4*)op;
    #pragma unroll
    for (int k = 0; k < TOPK; k++) {
        int s = g_slot[t * TOPK + k];
        if (s >= 0) {
            float wv = g_topk_w[t * TOPK + k];
            float4 y = *(const float4*)(g_y + (size_t)s * HID + h);
            acc.x += wv * y.x; acc.y += wv * y.y; acc.z += wv * y.z; acc.w += wv * y.w;
        }
    }
    *(float4*)op = acc;
}

// ---------------- entry ----------------
extern "C" void kernel_launch(void* const* d_in, const int* in_sizes, int n_in,
                              void* d_out, int out_size) {
    const float* x    = (const float*)d_in[0];
    const float* gw   = (const float*)d_in[1];
    const float* wgu  = (const float*)d_in[2];
    const float* wd   = (const float*)d_in[3];
    const float* wsgu = (const float*)d_in[4];
    const float* wsd  = (const float*)d_in[5];
    float* out = (float*)d_out;

    cudaFuncSetAttribute(k_mma_gateup, cudaFuncAttributeMaxDynamicSharedMemorySize, SMEM_DYN);
    cudaFuncSetAttribute(k_mma_down,   cudaFuncAttributeMaxDynamicSharedMemorySize, SMEM_DYN);

    k_gate    <<<T_TOK, 256>>>(x, gw);
    k_dispatch<<<1, 1024>>>();
    k_mma_gateup<<<dim3(IR / 64,  NE * (CAP / 128)), 256, SMEM_DYN>>>(x, wgu, 1, CAP, CAP / 128, HID, IR);
    k_mma_down  <<<dim3(HID / 128, NE * (CAP / 128)), 256, SMEM_DYN>>>(wd, nullptr, 1, CAP, CAP / 128, IR);
    k_mma_gateup<<<dim3(IS / 64,  T_TOK / 128), 256, SMEM_DYN>>>(x, wsgu, 0, T_TOK, T_TOK / 128, HID, IS);
    k_mma_down  <<<dim3(HID / 128, T_TOK / 128), 256, SMEM_DYN>>>(wsd, out, 0, T_TOK, T_TOK / 128, IS);
    k_combine <<<(T_TOK * HID / 4) / 256, 256>>>(out);
}

// round 5
// speedup vs baseline: 1.9108x; 1.0181x over previous
#include <cuda_runtime.h>
#include <cuda_bf16.h>
#include <math.h>
#include <stdint.h>

#define T_TOK 1024
#define HID   2048
#define NE    32
#define TOPK  6
#define NGRP  8
#define TGRP  3
#define IR    1408
#define IS    2816
#define CAP   384
#define RSCALE 16.0f

#define STAGE_BYTES 32768          // A 16KB + B 16KB
#define SMEM_DYN    65536          // 2 stages; reused as 128x128 fp32 epilogue

// ---------------- scratch (device globals: allocation-free) ----------------
__device__ int   g_topk_idx[T_TOK * TOPK];
__device__ float g_topk_w  [T_TOK * TOPK];
__device__ int   g_cnt     [NE];
__device__ int   g_rowtok  [NE * CAP];
__device__ int   g_slot    [T_TOK * TOPK];
__device__ float g_y       [(size_t)NE * CAP * HID];
__device__ unsigned short g_act_hi [(size_t)NE * CAP * IR];
__device__ unsigned short g_act_lo [(size_t)NE * CAP * IR];
__device__ unsigned short g_sact_hi[(size_t)T_TOK * IS];
__device__ unsigned short g_sact_lo[(size_t)T_TOK * IS];

// ---------------- helpers ----------------
__device__ __forceinline__ uint32_t smem_u32(const void* p) {
    uint32_t a;
    asm("{ .reg .u64 t; cvta.to.shared.u64 t, %1; cvt.u32.u64 %0, t; }" : "=r"(a) : "l"(p));
    return a;
}
#define SWZ(o) ((uint32_t)(o) ^ ((((uint32_t)(o)) >> 3) & 0x70u))

#define CP_ASYNC16(dst, src) \
    asm volatile("cp.async.cg.shared.global [%0], [%1], 16;" :: "r"(dst), "l"(src))
#define CP_COMMIT() asm volatile("cp.async.commit_group;" ::: "memory")
#define CP_WAIT0()  asm volatile("cp.async.wait_group 0;" ::: "memory")

__device__ __forceinline__ void ldsm4(uint32_t* r, uint32_t a) {
    asm volatile("ldmatrix.sync.aligned.m8n8.x4.shared.b16 {%0,%1,%2,%3}, [%4];"
        : "=r"(r[0]), "=r"(r[1]), "=r"(r[2]), "=r"(r[3]) : "r"(a));
}
__device__ __forceinline__ void ldsm4t(uint32_t* r, uint32_t a) {
    asm volatile("ldmatrix.sync.aligned.m8n8.x4.trans.shared.b16 {%0,%1,%2,%3}, [%4];"
        : "=r"(r[0]), "=r"(r[1]), "=r"(r[2]), "=r"(r[3]) : "r"(a));
}
__device__ __forceinline__ void mma16816(float* c, const uint32_t* a, const uint32_t* b) {
    asm volatile("mma.sync.aligned.m16n8k16.row.col.f32.bf16.bf16.f32 "
        "{%0,%1,%2,%3}, {%4,%5,%6,%7}, {%8,%9}, {%0,%1,%2,%3};"
        : "+f"(c[0]), "+f"(c[1]), "+f"(c[2]), "+f"(c[3])
        : "r"(a[0]), "r"(a[1]), "r"(a[2]), "r"(a[3]), "r"(b[0]), "r"(b[1]));
}

__device__ __forceinline__ void bsplit(float f, unsigned short& h, unsigned short& l) {
    __nv_bfloat16 bh = __float2bfloat16_rn(f);
    float fh = __bfloat162float(bh);
    __nv_bfloat16 bl = __float2bfloat16_rn(f - fh);
    h = __bfloat16_as_ushort(bh);
    l = __bfloat16_as_ushort(bl);
}
__device__ __forceinline__ uint32_t pack2(unsigned short a, unsigned short b) {
    return (uint32_t)a | ((uint32_t)b << 16);
}
__device__ __forceinline__ void split4(float4 v, uint2& h, uint2& l) {
    unsigned short h0,l0,h1,l1,h2,l2,h3,l3;
    bsplit(v.x,h0,l0); bsplit(v.y,h1,l1); bsplit(v.z,h2,l2); bsplit(v.w,h3,l3);
    h = make_uint2(pack2(h0,h1), pack2(h2,h3));
    l = make_uint2(pack2(l0,l1), pack2(l2,l3));
}

// ---------------- gate + routing (validated) ----------------
__global__ void k_gate(const float* __restrict__ x, const float* __restrict__ gw) {
    int t = blockIdx.x;
    __shared__ float xs[HID];
    __shared__ float lg[NE];
    const float* xr = x + (size_t)t * HID;
    for (int i = threadIdx.x; i < HID; i += 256) xs[i] = xr[i];
    __syncthreads();
    int e = threadIdx.x >> 3, j = threadIdx.x & 7;
    const float* w = gw + (size_t)e * HID;
    float s = 0.f;
    for (int i = j * 4; i < HID; i += 32) {
        float4 xv = *(const float4*)(xs + i);
        float4 wv = *(const float4*)(w + i);
        s += xv.x * wv.x + xv.y * wv.y + xv.z * wv.z + xv.w * wv.w;
    }
    #pragma unroll
    for (int off = 4; off; off >>= 1) s += __shfl_down_sync(0xffffffffu, s, off, 8);
    if (j == 0) lg[e] = s;
    __syncthreads();
    if (threadIdx.x == 0) {
        float gsc[NGRP]; int keep[NGRP];
        #pragma unroll
        for (int g2 = 0; g2 < NGRP; g2++) {
            float m4 = fmaxf(fmaxf(lg[g2*4], lg[g2*4+1]), fmaxf(lg[g2*4+2], lg[g2*4+3]));
            gsc[g2] = m4; keep[g2] = 0;
        }
        for (int it = 0; it < TGRP; it++) {
            float best = -INFINITY; int bi = 0;
            for (int g2 = 0; g2 < NGRP; g2++)
                if (!keep[g2] && gsc[g2] > best) { best = gsc[g2]; bi = g2; }
            keep[bi] = 1;
        }
        float sc[NE]; float mx = -INFINITY;
        for (int e2 = 0; e2 < NE; e2++) {
            float v = keep[e2 >> 2] ? lg[e2] : 0.0f;
            sc[e2] = v; mx = fmaxf(mx, v);
        }
        float sum = 0.f;
        for (int e2 = 0; e2 < NE; e2++) { float p = expf(sc[e2] - mx); sc[e2] = p; sum += p; }
        unsigned taken = 0u;
        for (int it = 0; it < TOPK; it++) {
            float best = -1.f; int bi = 0;
            for (int e2 = 0; e2 < NE; e2++)
                if (!((taken >> e2) & 1u) && sc[e2] > best) { best = sc[e2]; bi = e2; }
            taken |= 1u << bi;
            g_topk_idx[t * TOPK + it] = bi;
            g_topk_w  [t * TOPK + it] = (best / sum) * RSCALE;
        }
    }
}

__global__ void k_dispatch() {
    int w = threadIdx.x >> 5, lane = threadIdx.x & 31;
    int count = 0;
    for (int base = 0; base < T_TOK * TOPK; base += 32) {
        int idx = g_topk_idx[base + lane];
        unsigned m = __ballot_sync(0xffffffffu, idx == w);
        if (idx == w) {
            int pos = count + __popc(m & ((1u << lane) - 1u));
            int s = -1;
            if (pos < CAP) { s = w * CAP + pos; g_rowtok[s] = (base + lane) / TOPK; }
            g_slot[base + lane] = s;
        }
        count += __popc(m);
    }
    if (lane == 0) g_cnt[w] = count;
}

// =======================================================================
// MMA core: CTA 128x128, 8 warps (2Mx4N), K-chunk 32, bf16 split 3-product.
// SMEM stage: A [128 rows][128B: hi|lo] = 16KB; B @+16384: half h {hi 4KB, lo 4KB}
// =======================================================================
struct Frag { float c[4][4][4]; };

__device__ __forceinline__ void frag_zero(Frag& F) {
    #pragma unroll
    for (int mi = 0; mi < 4; mi++)
        #pragma unroll
        for (int ni = 0; ni < 4; ni++)
            #pragma unroll
            for (int q = 0; q < 4; q++) F.c[mi][ni][q] = 0.f;
}

__device__ __forceinline__ void mma_chunk(uint32_t sbs, int wm, int wn, int lane, Frag& F) {
    uint32_t Bh = sbs + 16384u + (uint32_t)(wn >> 1) * 8192u;
    #pragma unroll
    for (int kk = 0; kk < 2; kk++) {
        uint32_t ah[4][4], al[4][4], bh[2][4], bl[2][4];
        #pragma unroll
        for (int mi = 0; mi < 4; mi++) {
            uint32_t ro = (uint32_t)((wm * 64 + mi * 16 + (lane & 15)) * 128
                                     + kk * 32 + ((lane >> 4) * 16));
            ldsm4(ah[mi], sbs + SWZ(ro));
            ldsm4(al[mi], sbs + SWZ(ro + 64));
        }
        #pragma unroll
        for (int ng = 0; ng < 2; ng++) {
            uint32_t ro = (uint32_t)((kk * 16 + (lane & 15)) * 128
                                     + (wn & 1) * 64 + ng * 32 + ((lane >> 4) * 16));
            ldsm4t(bh[ng], Bh + SWZ(ro));
            ldsm4t(bl[ng], Bh + 4096u + SWZ(ro));
        }
        #pragma unroll
        for (int mi = 0; mi < 4; mi++)
            #pragma unroll
            for (int ni = 0; ni < 4; ni++) {
                const uint32_t* bhp = &bh[ni >> 1][(ni & 1) * 2];
                const uint32_t* blp = &bl[ni >> 1][(ni & 1) * 2];
                mma16816(F.c[mi][ni], ah[mi], bhp);
                mma16816(F.c[mi][ni], ah[mi], blp);
                mma16816(F.c[mi][ni], al[mi], bhp);
            }
    }
}

__device__ __forceinline__ void stage_accum(float* ep, int wm, int wn, int lane, Frag& F) {
    #pragma unroll
    for (int mi = 0; mi < 4; mi++)
        #pragma unroll
        for (int ni = 0; ni < 4; ni++) {
            int row = wm * 64 + mi * 16 + (lane >> 2);
            int col = wn * 32 + ni * 8 + ((lane & 3) << 1);
            ep[row * 128 + col]       = F.c[mi][ni][0];
            ep[row * 128 + col + 1]   = F.c[mi][ni][1];
            ep[(row + 8) * 128 + col]     = F.c[mi][ni][2];
            ep[(row + 8) * 128 + col + 1] = F.c[mi][ni][3];
        }
}

// =======================================================================
// gate_up GEMM + fused SiLU -> bf16 hi/lo activations
// =======================================================================
__global__ void __launch_bounds__(256, 1)
k_mma_gateup(const float* __restrict__ X, const float* __restrict__ B,
             int routed, int cap, int tilesM, int Kdim, int Ihalf)
{
    extern __shared__ char dsm[];
    __shared__ int rix_s[128];
    const int ldb = 2 * Ihalf;
    int tid = threadIdx.x, wid = tid >> 5, lane = tid & 31;
    int wm = wid & 1, wn = wid >> 1;
    int e = blockIdx.y / tilesM, mt = blockIdx.y % tilesM;
    int cb = blockIdx.x * 64;
    int rows = routed ? min(g_cnt[e], cap) : cap;
    int m0 = mt * 128;
    if (m0 >= rows) return;

    if (tid < 128) {
        int gm = m0 + tid;
        rix_s[tid] = (gm < rows) ? (routed ? g_rowtok[e * CAP + gm] : gm) : -1;
    }
    __syncthreads();

    const float* Bb = B + (size_t)e * Kdim * ldb;
    const int NCH = Kdim >> 5;

    Frag F; frag_zero(F);

    int arow = tid >> 3, ak4 = tid & 7;
    int bkr = tid >> 4, bn4 = tid & 15;
    float4 av[4], bv[4];

    // ---- loaders
    auto load_regs = [&](int c) {
        int k0 = c << 5;
        #pragma unroll
        for (int i = 0; i < 4; i++) {
            int rt = rix_s[arow + i * 32];
            av[i] = (rt >= 0) ? *(const float4*)(X + (size_t)rt * Kdim + k0 + ak4 * 4)
                              : make_float4(0.f, 0.f, 0.f, 0.f);
        }
        #pragma unroll
        for (int h = 0; h < 2; h++)
            #pragma unroll
            for (int j = 0; j < 2; j++)
                bv[h * 2 + j] = *(const float4*)(Bb + (size_t)(k0 + bkr + j * 16) * ldb
                                                 + h * Ihalf + cb + bn4 * 4);
    };
    auto sts_regs = [&](char* stg) {
        #pragma unroll
        for (int i = 0; i < 4; i++) {
            uint2 h2, l2; split4(av[i], h2, l2);
            int r = arow + i * 32;
            *(uint2*)(stg + SWZ(r * 128 + ak4 * 8)) = h2;
            *(uint2*)(stg + SWZ(r * 128 + 64 + ak4 * 8)) = l2;
        }
        #pragma unroll
        for (int h = 0; h < 2; h++)
            #pragma unroll
            for (int j = 0; j < 2; j++) {
                uint2 h2, l2; split4(bv[h * 2 + j], h2, l2);
                char* bb = stg + 16384 + h * 8192;
                uint32_t o = SWZ((bkr + j * 16) * 128 + bn4 * 8);
                *(uint2*)(bb + o) = h2;
                *(uint2*)(bb + 4096 + o) = l2;
            }
    };

    // ---- prologue
    load_regs(0);
    sts_regs(dsm);
    __syncthreads();

    // ---- mainloop: MMA(c) overlaps LDG(c+1) + STS(c+1, other buffer)
    for (int c = 0; c < NCH; c++) {
        if (c + 1 < NCH) load_regs(c + 1);
        mma_chunk(smem_u32(dsm + (c & 1) * STAGE_BYTES), wm, wn, lane, F);
        if (c + 1 < NCH) sts_regs(dsm + ((c + 1) & 1) * STAGE_BYTES);
        __syncthreads();
    }

    // ---- epilogue: accum -> smem fp32, silu(g)*u -> bf16 hi/lo -> gmem
    float* ep = (float*)dsm;
    stage_accum(ep, wm, wn, lane, F);
    __syncthreads();

    int m = tid >> 1, cs = (tid & 1) << 5;
    int rg = m0 + m;
    if (rg < rows) {
        unsigned short* Oh = routed ? g_act_hi : g_sact_hi;
        unsigned short* Ol = routed ? g_act_lo : g_sact_lo;
        size_t rowoff = ((size_t)(routed ? e * CAP : 0) + rg) * Ihalf + cb + cs;
        const float* gp = ep + m * 128 + cs;
        const float* up = gp + 64;
        uint32_t hi[16], lo[16];
        #pragma unroll
        for (int j = 0; j < 16; j++) {
            float g0 = gp[2*j],   u0 = up[2*j];
            float g1 = gp[2*j+1], u1 = up[2*j+1];
            float s0 = u0 * g0 / (1.f + expf(-g0));
            float s1 = u1 * g1 / (1.f + expf(-g1));
            unsigned short h0, l0, h1, l1;
            bsplit(s0, h0, l0); bsplit(s1, h1, l1);
            hi[j] = pack2(h0, h1); lo[j] = pack2(l0, l1);
        }
        #pragma unroll
        for (int j = 0; j < 4; j++) {
            *(uint4*)(Oh + rowoff + j * 8) = *(uint4*)(hi + j * 4);
            *(uint4*)(Ol + rowoff + j * 8) = *(uint4*)(lo + j * 4);
        }
    }
}

// =======================================================================
// down GEMM: act(bf16 hi/lo, via cp.async) @ Wd[K][HID] -> fp32
// =======================================================================
__global__ void __launch_bounds__(256, 1)
k_mma_down(const float* __restrict__ B, float* __restrict__ Oext,
           int routed, int cap, int tilesM, int Kdim)
{
    extern __shared__ char dsm[];
    int tid = threadIdx.x, wid = tid >> 5, lane = tid & 31;
    int wm = wid & 1, wn = wid >> 1;
    int e = blockIdx.y / tilesM, mt = blockIdx.y % tilesM;
    int n0 = blockIdx.x * 128;
    int rows = routed ? min(g_cnt[e], cap) : cap;
    int m0 = mt * 128;
    if (m0 >= rows) return;

    const unsigned short* Ah = routed ? g_act_hi : g_sact_hi;
    const unsigned short* Al = routed ? g_act_lo : g_sact_lo;
    size_t abase = ((size_t)(routed ? e * CAP : 0) + m0) * Kdim;
    const float* Bb = B + (size_t)e * Kdim * HID;
    const int NCH = Kdim >> 5;

    Frag F; frag_zero(F);

    int arow = tid >> 2, aq = tid & 3;
    int bkr = tid >> 4, bn4 = tid & 15;
    float4 bv[4];

    // A via cp.async straight into swizzled SMEM (already bf16 hi/lo)
    auto cp_a = [&](int c) {
        char* stg = dsm + (c & 1) * STAGE_BYTES;
        int k0 = c << 5;
        uint32_t sb = smem_u32(stg);
        #pragma unroll
        for (int i = 0; i < 2; i++) {
            int r = arow + i * 64;
            size_t off = abase + (size_t)r * Kdim + k0 + aq * 8;
            CP_ASYNC16(sb + SWZ(r * 128 + aq * 16), Ah + off);
            CP_ASYNC16(sb + SWZ(r * 128 + 64 + aq * 16), Al + off);
        }
        CP_COMMIT();
    };
    auto ldg_b = [&](int c) {
        int k0 = c << 5;
        #pragma unroll
        for (int h = 0; h < 2; h++)
            #pragma unroll
            for (int j = 0; j < 2; j++)
                bv[h * 2 + j] = *(const float4*)(Bb + (size_t)(k0 + bkr + j * 16) * HID
                                                 + n0 + h * 64 + bn4 * 4);
    };
    auto sts_b = [&](char* stg) {
        #pragma unroll
        for (int h = 0; h < 2; h++)
            #pragma unroll
            for (int j = 0; j < 2; j++) {
                uint2 h2, l2; split4(bv[h * 2 + j], h2, l2);
                char* bb = stg + 16384 + h * 8192;
                uint32_t o = SWZ((bkr + j * 16) * 128 + bn4 * 8);
                *(uint2*)(bb + o) = h2;
                *(uint2*)(bb + 4096 + o) = l2;
            }
    };

    // ---- prologue
    cp_a(0);
    ldg_b(0);
    sts_b(dsm);
    CP_WAIT0();
    __syncthreads();

    // ---- mainloop
    for (int c = 0; c < NCH; c++) {
        if (c + 1 < NCH) { cp_a(c + 1); ldg_b(c + 1); }
        mma_chunk(smem_u32(dsm + (c & 1) * STAGE_BYTES), wm, wn, lane, F);
        if (c + 1 < NCH) { sts_b(dsm + ((c + 1) & 1) * STAGE_BYTES); CP_WAIT0(); }
        __syncthreads();
    }

    // ---- epilogue
    float* ep = (float*)dsm;
    stage_accum(ep, wm, wn, lane, F);
    __syncthreads();

    int m = tid >> 1, cs = (tid & 1) << 6;
    int rg = m0 + m;
    if (rg < rows) {
        float* O = routed ? g_y : Oext;
        float* op = O + ((size_t)(routed ? e * CAP : 0) + rg) * HID + n0 + cs;
        const float* sp = ep + m * 128 + cs;
        #pragma unroll
        for (int j = 0; j < 16; j++)
            *(float4*)(op + j * 4) = *(const float4*)(sp + j * 4);
    }
}

// ---------------- combine ----------------
__global__ void k_combine(float* __restrict__ out) {
    int idx = blockIdx.x * 256 + threadIdx.x;
    int t = idx >> 9;
    int h = (idx & 511) << 2;
    float* op = out + (size_t)t * HID + h;
    float4 acc = *(float4*)op;
    #pragma unroll
    for (int k = 0; k < TOPK; k++) {
        int s = g_slot[t * TOPK + k];
        if (s >= 0) {
            float wv = g_topk_w[t * TOPK + k];
            float4 y = *(const float4*)(g_y + (size_t)s * HID + h);
            acc.x += wv * y.x; acc.y += wv * y.y; acc.z += wv * y.z; acc.w += wv * y.w;
        }
    }
    *(float4*)op = acc;
}

// ---------------- entry ----------------
extern "C" void kernel_launch(void* const* d_in, const int* in_sizes, int n_in,
                              void* d_out, int out_size) {
    const float* x    = (const float*)d_in[0];
    const float* gw   = (const float*)d_in[1];
    const float* wgu  = (const float*)d_in[2];
    const float* wd   = (const float*)d_in[3];
    const float* wsgu = (const float*)d_in[4];
    const float* wsd  = (const float*)d_in[5];
    float* out = (float*)d_out;

    cudaFuncSetAttribute(k_mma_gateup, cudaFuncAttributeMaxDynamicSharedMemorySize, SMEM_DYN);
    cudaFuncSetAttribute(k_mma_down,   cudaFuncAttributeMaxDynamicSharedMemorySize, SMEM_DYN);

    k_gate    <<<T_TOK, 256>>>(x, gw);
    k_dispatch<<<1, 1024>>>();
    k_mma_gateup<<<dim3(IR / 64,  NE * (CAP / 128)), 256, SMEM_DYN>>>(x, wgu, 1, CAP, CAP / 128, HID, IR);
    k_mma_down  <<<dim3(HID / 128, NE * (CAP / 128)), 256, SMEM_DYN>>>(wd, nullptr, 1, CAP, CAP / 128, IR);
    k_mma_gateup<<<dim3(IS / 64,  T_TOK / 128), 256, SMEM_DYN>>>(x, wsgu, 0, T_TOK, T_TOK / 128, HID, IS);
    k_mma_down  <<<dim3(HID / 128, T_TOK / 128), 256, SMEM_DYN>>>(wsd, out, 0, T_TOK, T_TOK / 128, IS);
    k_combine <<<(T_TOK * HID / 4) / 256, 256>>>(out);
}

// round 6
// speedup vs baseline: 2.0343x; 1.0646x over previous
#include <cuda_runtime.h>
#include <cuda_bf16.h>
#include <math.h>
#include <stdint.h>

#define T_TOK 1024
#define HID   2048
#define NE    32
#define TOPK  6
#define NGRP  8
#define TGRP  3
#define IR    1408
#define IS    2816
#define CAP   384
#define RSCALE 16.0f

#define STAGE_BYTES 32768          // A 16KB + B 16KB
#define SMEM_DYN    65536          // 2 stages; reused as 128x128 fp32 epilogue
#define NT 512                     // threads per GEMM CTA (16 warps)

// ---------------- scratch (device globals: allocation-free) ----------------
__device__ int   g_topk_idx[T_TOK * TOPK];
__device__ float g_topk_w  [T_TOK * TOPK];
__device__ int   g_cnt     [NE];
__device__ int   g_rowtok  [NE * CAP];
__device__ int   g_slot    [T_TOK * TOPK];
__device__ float g_y       [(size_t)NE * CAP * HID];
__device__ unsigned short g_act_hi [(size_t)NE * CAP * IR];
__device__ unsigned short g_act_lo [(size_t)NE * CAP * IR];
__device__ unsigned short g_sact_hi[(size_t)T_TOK * IS];
__device__ unsigned short g_sact_lo[(size_t)T_TOK * IS];

// ---------------- helpers ----------------
__device__ __forceinline__ uint32_t smem_u32(const void* p) {
    uint32_t a;
    asm("{ .reg .u64 t; cvta.to.shared.u64 t, %1; cvt.u32.u64 %0, t; }" : "=r"(a) : "l"(p));
    return a;
}
#define SWZ(o) ((uint32_t)(o) ^ ((((uint32_t)(o)) >> 3) & 0x70u))

#define CP_ASYNC16(dst, src) \
    asm volatile("cp.async.cg.shared.global [%0], [%1], 16;" :: "r"(dst), "l"(src))
#define CP_COMMIT() asm volatile("cp.async.commit_group;" ::: "memory")
#define CP_WAIT0()  asm volatile("cp.async.wait_group 0;" ::: "memory")

__device__ __forceinline__ void ldsm4(uint32_t* r, uint32_t a) {
    asm volatile("ldmatrix.sync.aligned.m8n8.x4.shared.b16 {%0,%1,%2,%3}, [%4];"
        : "=r"(r[0]), "=r"(r[1]), "=r"(r[2]), "=r"(r[3]) : "r"(a));
}
__device__ __forceinline__ void ldsm4t(uint32_t* r, uint32_t a) {
    asm volatile("ldmatrix.sync.aligned.m8n8.x4.trans.shared.b16 {%0,%1,%2,%3}, [%4];"
        : "=r"(r[0]), "=r"(r[1]), "=r"(r[2]), "=r"(r[3]) : "r"(a));
}
__device__ __forceinline__ void mma16816(float* c, const uint32_t* a, const uint32_t* b) {
    asm volatile("mma.sync.aligned.m16n8k16.row.col.f32.bf16.bf16.f32 "
        "{%0,%1,%2,%3}, {%4,%5,%6,%7}, {%8,%9}, {%0,%1,%2,%3};"
        : "+f"(c[0]), "+f"(c[1]), "+f"(c[2]), "+f"(c[3])
        : "r"(a[0]), "r"(a[1]), "r"(a[2]), "r"(a[3]), "r"(b[0]), "r"(b[1]));
}

__device__ __forceinline__ void bsplit(float f, unsigned short& h, unsigned short& l) {
    __nv_bfloat16 bh = __float2bfloat16_rn(f);
    float fh = __bfloat162float(bh);
    __nv_bfloat16 bl = __float2bfloat16_rn(f - fh);
    h = __bfloat16_as_ushort(bh);
    l = __bfloat16_as_ushort(bl);
}
__device__ __forceinline__ uint32_t pack2(unsigned short a, unsigned short b) {
    return (uint32_t)a | ((uint32_t)b << 16);
}
__device__ __forceinline__ void split4(float4 v, uint2& h, uint2& l) {
    unsigned short h0,l0,h1,l1,h2,l2,h3,l3;
    bsplit(v.x,h0,l0); bsplit(v.y,h1,l1); bsplit(v.z,h2,l2); bsplit(v.w,h3,l3);
    h = make_uint2(pack2(h0,h1), pack2(h2,h3));
    l = make_uint2(pack2(l0,l1), pack2(l2,l3));
}

// ---------------- gate + routing (validated) ----------------
__global__ void k_gate(const float* __restrict__ x, const float* __restrict__ gw) {
    int t = blockIdx.x;
    __shared__ float xs[HID];
    __shared__ float lg[NE];
    const float* xr = x + (size_t)t * HID;
    for (int i = threadIdx.x; i < HID; i += 256) xs[i] = xr[i];
    __syncthreads();
    int e = threadIdx.x >> 3, j = threadIdx.x & 7;
    const float* w = gw + (size_t)e * HID;
    float s = 0.f;
    for (int i = j * 4; i < HID; i += 32) {
        float4 xv = *(const float4*)(xs + i);
        float4 wv = *(const float4*)(w + i);
        s += xv.x * wv.x + xv.y * wv.y + xv.z * wv.z + xv.w * wv.w;
    }
    #pragma unroll
    for (int off = 4; off; off >>= 1) s += __shfl_down_sync(0xffffffffu, s, off, 8);
    if (j == 0) lg[e] = s;
    __syncthreads();
    if (threadIdx.x == 0) {
        float gsc[NGRP]; int keep[NGRP];
        #pragma unroll
        for (int g2 = 0; g2 < NGRP; g2++) {
            float m4 = fmaxf(fmaxf(lg[g2*4], lg[g2*4+1]), fmaxf(lg[g2*4+2], lg[g2*4+3]));
            gsc[g2] = m4; keep[g2] = 0;
        }
        for (int it = 0; it < TGRP; it++) {
            float best = -INFINITY; int bi = 0;
            for (int g2 = 0; g2 < NGRP; g2++)
                if (!keep[g2] && gsc[g2] > best) { best = gsc[g2]; bi = g2; }
            keep[bi] = 1;
        }
        float sc[NE]; float mx = -INFINITY;
        for (int e2 = 0; e2 < NE; e2++) {
            float v = keep[e2 >> 2] ? lg[e2] : 0.0f;
            sc[e2] = v; mx = fmaxf(mx, v);
        }
        float sum = 0.f;
        for (int e2 = 0; e2 < NE; e2++) { float p = expf(sc[e2] - mx); sc[e2] = p; sum += p; }
        unsigned taken = 0u;
        for (int it = 0; it < TOPK; it++) {
            float best = -1.f; int bi = 0;
            for (int e2 = 0; e2 < NE; e2++)
                if (!((taken >> e2) & 1u) && sc[e2] > best) { best = sc[e2]; bi = e2; }
            taken |= 1u << bi;
            g_topk_idx[t * TOPK + it] = bi;
            g_topk_w  [t * TOPK + it] = (best / sum) * RSCALE;
        }
    }
}

__global__ void k_dispatch() {
    int w = threadIdx.x >> 5, lane = threadIdx.x & 31;
    int count = 0;
    for (int base = 0; base < T_TOK * TOPK; base += 32) {
        int idx = g_topk_idx[base + lane];
        unsigned m = __ballot_sync(0xffffffffu, idx == w);
        if (idx == w) {
            int pos = count + __popc(m & ((1u << lane) - 1u));
            int s = -1;
            if (pos < CAP) { s = w * CAP + pos; g_rowtok[s] = (base + lane) / TOPK; }
            g_slot[base + lane] = s;
        }
        count += __popc(m);
    }
    if (lane == 0) g_cnt[w] = count;
}

// =======================================================================
// MMA core: CTA 128x128, 16 warps (4Mx4N), warp tile 32x32, K-chunk 32,
// bf16 split 3-product. SMEM stage: A [128][128B hi|lo] = 16KB;
// B @+16384: half h {hi 4KB @h*8192, lo 4KB @+4096}.
// =======================================================================
__device__ __forceinline__ void mma_chunk(uint32_t sbs, int wm, int wn, int lane,
                                          float c[2][4][4]) {
    uint32_t Bh = sbs + 16384u + (uint32_t)(wn >> 1) * 8192u;
    #pragma unroll
    for (int kk = 0; kk < 2; kk++) {
        uint32_t ah[2][4], al[2][4], bh[2][4], bl[2][4];
        #pragma unroll
        for (int mi = 0; mi < 2; mi++) {
            uint32_t ro = (uint32_t)((wm * 32 + mi * 16 + (lane & 15)) * 128
                                     + kk * 32 + ((lane >> 4) * 16));
            ldsm4(ah[mi], sbs + SWZ(ro));
            ldsm4(al[mi], sbs + SWZ(ro + 64));
        }
        #pragma unroll
        for (int ng = 0; ng < 2; ng++) {
            uint32_t ro = (uint32_t)((kk * 16 + (lane & 15)) * 128
                                     + (wn & 1) * 64 + ng * 32 + ((lane >> 4) * 16));
            ldsm4t(bh[ng], Bh + SWZ(ro));
            ldsm4t(bl[ng], Bh + 4096u + SWZ(ro));
        }
        #pragma unroll
        for (int mi = 0; mi < 2; mi++)
            #pragma unroll
            for (int ni = 0; ni < 4; ni++) {
                const uint32_t* bhp = &bh[ni >> 1][(ni & 1) * 2];
                const uint32_t* blp = &bl[ni >> 1][(ni & 1) * 2];
                mma16816(c[mi][ni], ah[mi], bhp);
                mma16816(c[mi][ni], ah[mi], blp);
                mma16816(c[mi][ni], al[mi], bhp);
            }
    }
}

__device__ __forceinline__ void stage_accum(float* ep, int wm, int wn, int lane,
                                            float c[2][4][4]) {
    #pragma unroll
    for (int mi = 0; mi < 2; mi++)
        #pragma unroll
        for (int ni = 0; ni < 4; ni++) {
            int row = wm * 32 + mi * 16 + (lane >> 2);
            int col = wn * 32 + ni * 8 + ((lane & 3) << 1);
            ep[row * 128 + col]           = c[mi][ni][0];
            ep[row * 128 + col + 1]       = c[mi][ni][1];
            ep[(row + 8) * 128 + col]     = c[mi][ni][2];
            ep[(row + 8) * 128 + col + 1] = c[mi][ni][3];
        }
}

// =======================================================================
// gate_up GEMM + fused SiLU -> bf16 hi/lo activations
// =======================================================================
__global__ void __launch_bounds__(NT, 1)
k_mma_gateup(const float* __restrict__ X, const float* __restrict__ B,
             int routed, int cap, int tilesM, int Kdim, int Ihalf)
{
    extern __shared__ char dsm[];
    __shared__ int rix_s[128];
    const int ldb = 2 * Ihalf;
    int tid = threadIdx.x, wid = tid >> 5, lane = tid & 31;
    int wm = wid & 3, wn = wid >> 2;
    int e = blockIdx.y / tilesM, mt = blockIdx.y % tilesM;
    int cb = blockIdx.x * 64;
    int rows = routed ? min(g_cnt[e], cap) : cap;
    int m0 = mt * 128;
    if (m0 >= rows) return;

    if (tid < 128) {
        int gm = m0 + tid;
        rix_s[tid] = (gm < rows) ? (routed ? g_rowtok[e * CAP + gm] : gm) : -1;
    }
    __syncthreads();

    const float* Bb = B + (size_t)e * Kdim * ldb;
    const int NCH = Kdim >> 5;

    float F[2][4][4];
    #pragma unroll
    for (int mi = 0; mi < 2; mi++)
        #pragma unroll
        for (int ni = 0; ni < 4; ni++)
            #pragma unroll
            for (int q = 0; q < 4; q++) F[mi][ni][q] = 0.f;

    int arow = tid >> 2, aq = tid & 3;           // 4 threads/row, 8 floats each
    int bkr = tid >> 4, bn4 = tid & 15;          // 16 threads/krow, 4 floats/half
    float4 av[2], bv[2];

    auto load_regs = [&](int c) {
        int k0 = c << 5;
        int rt = rix_s[arow];
        if (rt >= 0) {
            const float* ap = X + (size_t)rt * Kdim + k0 + aq * 8;
            av[0] = *(const float4*)ap;
            av[1] = *(const float4*)(ap + 4);
        } else {
            av[0] = av[1] = make_float4(0.f, 0.f, 0.f, 0.f);
        }
        #pragma unroll
        for (int h = 0; h < 2; h++)
            bv[h] = *(const float4*)(Bb + (size_t)(k0 + bkr) * ldb + h * Ihalf + cb + bn4 * 4);
    };
    auto sts_regs = [&](char* stg) {
        uint2 h0, l0, h1, l1;
        split4(av[0], h0, l0); split4(av[1], h1, l1);
        uint4 hv = make_uint4(h0.x, h0.y, h1.x, h1.y);
        uint4 lv = make_uint4(l0.x, l0.y, l1.x, l1.y);
        *(uint4*)(stg + SWZ(arow * 128 + aq * 16)) = hv;
        *(uint4*)(stg + SWZ(arow * 128 + 64 + aq * 16)) = lv;
        #pragma unroll
        for (int h = 0; h < 2; h++) {
            uint2 h2, l2; split4(bv[h], h2, l2);
            char* bb = stg + 16384 + h * 8192;
            uint32_t o = SWZ(bkr * 128 + bn4 * 8);
            *(uint2*)(bb + o) = h2;
            *(uint2*)(bb + 4096 + o) = l2;
        }
    };

    load_regs(0);
    sts_regs(dsm);
    __syncthreads();

    for (int c = 0; c < NCH; c++) {
        if (c + 1 < NCH) load_regs(c + 1);
        mma_chunk(smem_u32(dsm + (c & 1) * STAGE_BYTES), wm, wn, lane, F);
        if (c + 1 < NCH) sts_regs(dsm + ((c + 1) & 1) * STAGE_BYTES);
        __syncthreads();
    }

    // ---- epilogue: accum -> smem fp32, silu(g)*u -> bf16 hi/lo -> gmem
    float* ep = (float*)dsm;
    stage_accum(ep, wm, wn, lane, F);
    __syncthreads();

    int m = tid >> 2, seg = tid & 3;             // 16 gate cols per thread
    int rg = m0 + m;
    if (rg < rows) {
        unsigned short* Oh = routed ? g_act_hi : g_sact_hi;
        unsigned short* Ol = routed ? g_act_lo : g_sact_lo;
        size_t rowoff = ((size_t)(routed ? e * CAP : 0) + rg) * Ihalf + cb + seg * 16;
        const float* gp = ep + m * 128 + seg * 16;
        const float* up = gp + 64;
        uint32_t hi[8], lo[8];
        #pragma unroll
        for (int j = 0; j < 8; j++) {
            float g0 = gp[2*j],   u0 = up[2*j];
            float g1 = gp[2*j+1], u1 = up[2*j+1];
            float s0 = u0 * g0 / (1.f + expf(-g0));
            float s1 = u1 * g1 / (1.f + expf(-g1));
            unsigned short h0, l0, h1, l1;
            bsplit(s0, h0, l0); bsplit(s1, h1, l1);
            hi[j] = pack2(h0, h1); lo[j] = pack2(l0, l1);
        }
        #pragma unroll
        for (int j = 0; j < 2; j++) {
            *(uint4*)(Oh + rowoff + j * 8) = *(uint4*)(hi + j * 4);
            *(uint4*)(Ol + rowoff + j * 8) = *(uint4*)(lo + j * 4);
        }
    }
}

// =======================================================================
// down GEMM: act(bf16 hi/lo, via cp.async) @ Wd[K][HID] -> fp32
// =======================================================================
__global__ void __launch_bounds__(NT, 1)
k_mma_down(const float* __restrict__ B, float* __restrict__ Oext,
           int routed, int cap, int tilesM, int Kdim)
{
    extern __shared__ char dsm[];
    int tid = threadIdx.x, wid = tid >> 5, lane = tid & 31;
    int wm = wid & 3, wn = wid >> 2;
    int e = blockIdx.y / tilesM, mt = blockIdx.y % tilesM;
    int n0 = blockIdx.x * 128;
    int rows = routed ? min(g_cnt[e], cap) : cap;
    int m0 = mt * 128;
    if (m0 >= rows) return;

    const unsigned short* Ah = routed ? g_act_hi : g_sact_hi;
    const unsigned short* Al = routed ? g_act_lo : g_sact_lo;
    size_t abase = ((size_t)(routed ? e * CAP : 0) + m0) * Kdim;
    const float* Bb = B + (size_t)e * Kdim * HID;
    const int NCH = Kdim >> 5;

    float F[2][4][4];
    #pragma unroll
    for (int mi = 0; mi < 2; mi++)
        #pragma unroll
        for (int ni = 0; ni < 4; ni++)
            #pragma unroll
            for (int q = 0; q < 4; q++) F[mi][ni][q] = 0.f;

    int arow = tid >> 2, aq = tid & 3;
    int bkr = tid >> 4, bn4 = tid & 15;
    float4 bv[2];

    auto cp_a = [&](int c) {
        char* stg = dsm + (c & 1) * STAGE_BYTES;
        int k0 = c << 5;
        uint32_t sb = smem_u32(stg);
        size_t off = abase + (size_t)arow * Kdim + k0 + aq * 8;
        CP_ASYNC16(sb + SWZ(arow * 128 + aq * 16), Ah + off);
        CP_ASYNC16(sb + SWZ(arow * 128 + 64 + aq * 16), Al + off);
        CP_COMMIT();
    };
    auto ldg_b = [&](int c) {
        int k0 = c << 5;
        #pragma unroll
        for (int h = 0; h < 2; h++)
            bv[h] = *(const float4*)(Bb + (size_t)(k0 + bkr) * HID + n0 + h * 64 + bn4 * 4);
    };
    auto sts_b = [&](char* stg) {
        #pragma unroll
        for (int h = 0; h < 2; h++) {
            uint2 h2, l2; split4(bv[h], h2, l2);
            char* bb = stg + 16384 + h * 8192;
            uint32_t o = SWZ(bkr * 128 + bn4 * 8);
            *(uint2*)(bb + o) = h2;
            *(uint2*)(bb + 4096 + o) = l2;
        }
    };

    cp_a(0);
    ldg_b(0);
    sts_b(dsm);
    CP_WAIT0();
    __syncthreads();

    for (int c = 0; c < NCH; c++) {
        if (c + 1 < NCH) { cp_a(c + 1); ldg_b(c + 1); }
        mma_chunk(smem_u32(dsm + (c & 1) * STAGE_BYTES), wm, wn, lane, F);
        if (c + 1 < NCH) { sts_b(dsm + ((c + 1) & 1) * STAGE_BYTES); CP_WAIT0(); }
        __syncthreads();
    }

    // ---- epilogue
    float* ep = (float*)dsm;
    stage_accum(ep, wm, wn, lane, F);
    __syncthreads();

    int m = tid >> 2, cs = (tid & 3) << 5;
    int rg = m0 + m;
    if (rg < rows) {
        float* O = routed ? g_y : Oext;
        float* op = O + ((size_t)(routed ? e * CAP : 0) + rg) * HID + n0 + cs;
        const float* sp = ep + m * 128 + cs;
        #pragma unroll
        for (int j = 0; j < 8; j++)
            *(float4*)(op + j * 4) = *(const float4*)(sp + j * 4);
    }
}

// ---------------- combine ----------------
__global__ void k_combine(float* __restrict__ out) {
    int idx = blockIdx.x * 256 + threadIdx.x;
    int t = idx >> 9;
    int h = (idx & 511) << 2;
    float* op = out + (size_t)t * HID + h;
    float4 acc = *(float4*)op;
    #pragma unroll
    for (int k = 0; k < TOPK; k++) {
        int s = g_slot[t * TOPK + k];
        if (s >= 0) {
            float wv = g_topk_w[t * TOPK + k];
            float4 y = *(const float4*)(g_y + (size_t)s * HID + h);
            acc.x += wv * y.x; acc.y += wv * y.y; acc.z += wv * y.z; acc.w += wv * y.w;
        }
    }
    *(float4*)op = acc;
}

// ---------------- entry ----------------
extern "C" void kernel_launch(void* const* d_in, const int* in_sizes, int n_in,
                              void* d_out, int out_size) {
    const float* x    = (const float*)d_in[0];
    const float* gw   = (const float*)d_in[1];
    const float* wgu  = (const float*)d_in[2];
    const float* wd   = (const float*)d_in[3];
    const float* wsgu = (const float*)d_in[4];
    const float* wsd  = (const float*)d_in[5];
    float* out = (float*)d_out;

    cudaFuncSetAttribute(k_mma_gateup, cudaFuncAttributeMaxDynamicSharedMemorySize, SMEM_DYN);
    cudaFuncSetAttribute(k_mma_down,   cudaFuncAttributeMaxDynamicSharedMemorySize, SMEM_DYN);

    k_gate    <<<T_TOK, 256>>>(x, gw);
    k_dispatch<<<1, 1024>>>();
    k_mma_gateup<<<dim3(IR / 64,  NE * (CAP / 128)), NT, SMEM_DYN>>>(x, wgu, 1, CAP, CAP / 128, HID, IR);
    k_mma_down  <<<dim3(HID / 128, NE * (CAP / 128)), NT, SMEM_DYN>>>(wd, nullptr, 1, CAP, CAP / 128, IR);
    k_mma_gateup<<<dim3(IS / 64,  T_TOK / 128), NT, SMEM_DYN>>>(x, wsgu, 0, T_TOK, T_TOK / 128, HID, IS);
    k_mma_down  <<<dim3(HID / 128, T_TOK / 128), NT, SMEM_DYN>>>(wsd, out, 0, T_TOK, T_TOK / 128, IS);
    k_combine <<<(T_TOK * HID / 4) / 256, 256>>>(out);
}